// round 6
// baseline (speedup 1.0000x reference)
#include <cuda_runtime.h>
#include <math_constants.h>

// contributions: [S=256, P=2000, C=200] fp32, row-major (c contiguous).
// Per (s, c) column along P: zero the top-4 (stable ties -> lower p), pass rest.
//
// R5: R4 structure (1 thread = 1 column-segment, 4 warps/32 cols per block,
// 204800 threads, batched max-reject) + address strength reduction: base
// pointers advance by U*C once per batch; element accesses use compile-time
// immediate offsets (u*C) so LDG/STG carry no per-element address math.

static constexpr int S = 256;
static constexpr int P = 2000;
static constexpr int C = 200;
static constexpr int NCOL = S * C;          // 51200 columns
static constexpr int SEG  = 4;              // segments (warps) per column group
static constexpr int PSEG = P / SEG;        // 500
static constexpr int U    = 10;             // 500 = 50 * 10
static constexpr int NB   = PSEG / U;       // 50 batches
static constexpr int COLS = 32;             // columns per block
static constexpr int BLK  = COLS * SEG;     // 128 threads
static constexpr int GRID = NCOL / COLS;    // 1600 blocks

__global__ void __launch_bounds__(BLK)
numproto_topk_zero(const float* __restrict__ in, float* __restrict__ out) {
    const int tid  = threadIdx.x;
    const int seg  = tid >> 5;              // 0..3
    const int lane = tid & 31;
    const int col  = blockIdx.x * COLS + lane;

    const int s = col / C;
    const int c = col - s * C;

    const int p0 = seg * PSEG;
    const float* __restrict__ ipp = in  + (size_t)s * P * C + c + (size_t)p0 * C;
    float*       __restrict__ opp = out + (size_t)s * P * C + c + (size_t)p0 * C;

    float t0 = -CUDART_INF_F, t1 = -CUDART_INF_F,
          t2 = -CUDART_INF_F, t3 = -CUDART_INF_F;
    int   i0 = 0, i1 = 0, i2 = 0, i3 = 0;

    int pbase = p0;
    for (int it = 0; it < NB; it++) {
        float v[U];
        #pragma unroll
        for (int u = 0; u < U; u++)
            v[u] = ipp[u * C];              // immediate offsets, no addr math
        #pragma unroll
        for (int u = 0; u < U; u++)
            opp[u * C] = v[u];

        // batched rejection: one branch per 10 elements
        float m01 = fmaxf(v[0], v[1]);
        float m23 = fmaxf(v[2], v[3]);
        float m45 = fmaxf(v[4], v[5]);
        float m67 = fmaxf(v[6], v[7]);
        float m89 = fmaxf(v[8], v[9]);
        float mx  = fmaxf(fmaxf(fmaxf(m01, m23), fmaxf(m45, m67)), m89);

        if (mx > t3) {  // rare after warm-up
            #pragma unroll
            for (int u = 0; u < U; u++) {
                float vv = v[u];
                if (vv > t3) {
                    int pp = pbase + u;
                    if (vv > t0) {
                        t3 = t2; i3 = i2; t2 = t1; i2 = i1; t1 = t0; i1 = i0;
                        t0 = vv; i0 = pp;
                    } else if (vv > t1) {
                        t3 = t2; i3 = i2; t2 = t1; i2 = i1;
                        t1 = vv; i1 = pp;
                    } else if (vv > t2) {
                        t3 = t2; i3 = i2;
                        t2 = vv; i2 = pp;
                    } else {
                        t3 = vv; i3 = pp;
                    }
                }
            }
        }
        ipp += U * C;
        opp += U * C;
        pbase += U;
    }

    // candidate exchange: [seg][rank][col] -> conflict-free both phases
    __shared__ float sv[SEG][4][COLS];
    __shared__ int   si[SEG][4][COLS];
    sv[seg][0][lane] = t0; si[seg][0][lane] = i0;
    sv[seg][1][lane] = t1; si[seg][1][lane] = i1;
    sv[seg][2][lane] = t2; si[seg][2][lane] = i2;
    sv[seg][3][lane] = t3; si[seg][3][lane] = i3;

    __syncthreads();   // also orders this block's copy-stores before the patch

    if (tid < COLS) {
        const int pcol = blockIdx.x * COLS + tid;
        const int ps   = pcol / C;
        const int pc   = pcol - ps * C;
        float* opc = out + (size_t)ps * P * C + pc;

        float m0 = -CUDART_INF_F, m1 = -CUDART_INF_F,
              m2 = -CUDART_INF_F, m3 = -CUDART_INF_F;
        int   j0 = 0x7fffffff, j1 = 0x7fffffff,
              j2 = 0x7fffffff, j3 = 0x7fffffff;
        #pragma unroll
        for (int sg = 0; sg < SEG; sg++) {
            #pragma unroll
            for (int k = 0; k < 4; k++) {
                float v = sv[sg][k][tid];
                int   i = si[sg][k][tid];
                if (v > m3 || (v == m3 && i < j3)) {
                    if (v > m0 || (v == m0 && i < j0)) {
                        m3 = m2; j3 = j2; m2 = m1; j2 = j1; m1 = m0; j1 = j0;
                        m0 = v;  j0 = i;
                    } else if (v > m1 || (v == m1 && i < j1)) {
                        m3 = m2; j3 = j2; m2 = m1; j2 = j1;
                        m1 = v;  j1 = i;
                    } else if (v > m2 || (v == m2 && i < j2)) {
                        m3 = m2; j3 = j2;
                        m2 = v;  j2 = i;
                    } else {
                        m3 = v;  j3 = i;
                    }
                }
            }
        }
        opc[(size_t)j0 * C] = 0.0f;
        opc[(size_t)j1 * C] = 0.0f;
        opc[(size_t)j2 * C] = 0.0f;
        opc[(size_t)j3 * C] = 0.0f;
    }
}

extern "C" void kernel_launch(void* const* d_in, const int* in_sizes, int n_in,
                              void* d_out, int out_size) {
    (void)in_sizes; (void)n_in; (void)out_size;
    const float* in  = (const float*)d_in[0];
    float*       out = (float*)d_out;
    numproto_topk_zero<<<GRID, BLK>>>(in, out);
}